// round 1
// baseline (speedup 1.0000x reference)
#include <cuda_runtime.h>
#include <math.h>

// Problem constants
#define Bx  2
#define Lx  2048
#define Dx  1024
#define Hx  16
#define DKx 64
#define BHx (Bx*Hx)

// ---------------- device scratch (no allocations allowed) ----------------
__device__ float g_Q[(size_t)BHx*Lx*DKx];      // [B,H,L,DK]
__device__ float g_K[(size_t)BHx*Lx*DKx];
__device__ float g_V[(size_t)BHx*Lx*DKx];
__device__ float g_attn[(size_t)Bx*Lx*Dx];     // [B,L,H*DK]
__device__ float g_bias[(size_t)Bx*Lx*Lx];     // -|lam|*log1p(|ti-tj|/denom)
__device__ float g_scal[2];                    // [0]=1/denom, [1]=-|lam|

// ---------------- denom + lam scalars ----------------
__global__ void k_denom(const float* __restrict__ ts, const float* __restrict__ lam)
{
    // timestamps are sorted ascending along L, so max |ti-tj| per batch = t[L-1]-t[0]
    float m = 1.0f;
    for (int b = 0; b < Bx; b++) {
        float d = ts[b*Lx + (Lx-1)] - ts[b*Lx + 0];
        m = fmaxf(m, d);
    }
    g_scal[0] = 1.0f / m;
    g_scal[1] = -fabsf(lam[0]);
}

// ---------------- temporal bias precompute ----------------
__global__ __launch_bounds__(256) void k_bias(const float* __restrict__ ts)
{
    long idx = (long)blockIdx.x * 256 + threadIdx.x;   // over B*L*L, exact multiple
    int  j = (int)(idx & (Lx-1));
    long t = idx >> 11;
    int  i = (int)(t & (Lx-1));
    int  b = (int)(t >> 11);
    float d = fabsf(ts[b*Lx + i] - ts[b*Lx + j]);
    g_bias[idx] = g_scal[1] * log1pf(d * g_scal[0]);
}

// ---------------- tiled fp32 GEMM:  out[m,n] = sum_k A[m,k]*W[n,k] + bias[n] ----------------
// BM=BN=128, BK=16, 256 threads, 8x8 microtiles.
// SCATTER=true : three outputs (Q,K,V) selected by blockIdx.z, written as [B,H,L,DK]
// SCATTER=false: A = g_attn, plain row-major write to outp
template<bool SCATTER>
__global__ __launch_bounds__(256) void k_gemm(
    const float* __restrict__ Ain,
    const float* __restrict__ W0, const float* __restrict__ b0,
    const float* __restrict__ W1, const float* __restrict__ b1,
    const float* __restrict__ W2, const float* __restrict__ b2,
    float* __restrict__ outp)
{
    __shared__ float As[16][132];
    __shared__ float Bs[16][132];

    const float* A;
    const float* W;
    const float* bias;
    float* out;
    if (SCATTER) {
        A = Ain;
        if (blockIdx.z == 0)      { W = W0; bias = b0; out = g_Q; }
        else if (blockIdx.z == 1) { W = W1; bias = b1; out = g_K; }
        else                      { W = W2; bias = b2; out = g_V; }
    } else {
        A = g_attn; W = W0; bias = b0; out = outp;
    }

    const int tid = threadIdx.x;
    const int ty = tid >> 4, tx = tid & 15;
    const int m0 = blockIdx.y * 128, n0 = blockIdx.x * 128;

    float acc[8][8];
#pragma unroll
    for (int i = 0; i < 8; i++)
#pragma unroll
        for (int j = 0; j < 8; j++) acc[i][j] = 0.f;

    for (int k0 = 0; k0 < Dx; k0 += 16) {
#pragma unroll
        for (int t = 0; t < 2; t++) {
            int idx = tid + t*256;            // 0..511
            int row = idx >> 2, q = idx & 3;
            float4 va = *(const float4*)(A + (size_t)(m0+row)*Dx + k0 + q*4);
            As[q*4+0][row] = va.x; As[q*4+1][row] = va.y;
            As[q*4+2][row] = va.z; As[q*4+3][row] = va.w;
            float4 vb = *(const float4*)(W + (size_t)(n0+row)*Dx + k0 + q*4);
            Bs[q*4+0][row] = vb.x; Bs[q*4+1][row] = vb.y;
            Bs[q*4+2][row] = vb.z; Bs[q*4+3][row] = vb.w;
        }
        __syncthreads();
#pragma unroll
        for (int kk = 0; kk < 16; kk++) {
            float a[8], bb[8];
            *(float4*)&a[0]  = *(const float4*)&As[kk][ty*8];
            *(float4*)&a[4]  = *(const float4*)&As[kk][ty*8+4];
            *(float4*)&bb[0] = *(const float4*)&Bs[kk][tx*8];
            *(float4*)&bb[4] = *(const float4*)&Bs[kk][tx*8+4];
#pragma unroll
            for (int i = 0; i < 8; i++)
#pragma unroll
                for (int j = 0; j < 8; j++)
                    acc[i][j] += a[i] * bb[j];
        }
        __syncthreads();
    }

#pragma unroll
    for (int i = 0; i < 8; i++) {
        int m = m0 + ty*8 + i;
        int b_ = m >> 11;          // / L
        int l  = m & (Lx-1);
#pragma unroll
        for (int j = 0; j < 8; j++) {
            int n = n0 + tx*8 + j;
            float v = acc[i][j] + bias[n];
            if (SCATTER) {
                int h = n >> 6, dk = n & 63;
                out[(((size_t)b_*Hx + h)*Lx + l)*DKx + dk] = v;
            } else {
                out[(size_t)m*Dx + n] = v;
            }
        }
    }
}

// ---------------- fp32 causal flash attention with temporal bias ----------------
// One block handles 64 query rows of one (b,h). 256 threads (16x16), each owns a
// 4x4 tile of S and of O (DK=64 columns map to the same 16x4 column split).
__global__ __launch_bounds__(256) void k_attn()
{
    extern __shared__ float sm[];
    float* Qst = sm;               // [64 d][68] transposed Q tile
    float* KPb = sm + 64*68;       // K transposed [d][68], reused as P [r][68]
    float* Vs  = sm + 2*64*68;     // [64 k][64] natural

    const int tid = threadIdx.x;
    const int ty = tid >> 4, tx = tid & 15;
    const int qt = blockIdx.x;
    const int bh = blockIdx.y;
    const int b  = bh >> 4, h = bh & 15;
    const int qi0 = qt * 64;

    const float* Qg = g_Q + (size_t)bh*Lx*DKx + (size_t)qi0*DKx;
    const float* Kg = g_K + (size_t)bh*Lx*DKx;
    const float* Vg = g_V + (size_t)bh*Lx*DKx;
    const float* biasB = g_bias + (size_t)b*Lx*Lx;

    // load Q tile transposed: Qst[d][r]
#pragma unroll
    for (int t = 0; t < 4; t++) {
        int idx = tid + t*256;          // 0..1023
        int r = idx >> 4, d4 = idx & 15;
        float4 v = *(const float4*)(Qg + (size_t)r*DKx + d4*4);
        Qst[(d4*4+0)*68 + r] = v.x;
        Qst[(d4*4+1)*68 + r] = v.y;
        Qst[(d4*4+2)*68 + r] = v.z;
        Qst[(d4*4+3)*68 + r] = v.w;
    }

    float m_i[4], l_i[4], O[4][4];
#pragma unroll
    for (int i = 0; i < 4; i++) {
        m_i[i] = -1e30f; l_i[i] = 0.f;
#pragma unroll
        for (int j = 0; j < 4; j++) O[i][j] = 0.f;
    }

    for (int jt = 0; jt <= qt; jt++) {
        const int kj0 = jt * 64;
        __syncthreads();   // protect KPb/Vs from previous iteration's readers
#pragma unroll
        for (int t = 0; t < 4; t++) {
            int idx = tid + t*256;
            int r = idx >> 4, d4 = idx & 15;
            float4 kv = *(const float4*)(Kg + (size_t)(kj0+r)*DKx + d4*4);
            KPb[(d4*4+0)*68 + r] = kv.x;
            KPb[(d4*4+1)*68 + r] = kv.y;
            KPb[(d4*4+2)*68 + r] = kv.z;
            KPb[(d4*4+3)*68 + r] = kv.w;
            float4 vv = *(const float4*)(Vg + (size_t)(kj0+r)*DKx + d4*4);
            *(float4*)(Vs + r*64 + d4*4) = vv;
        }
        __syncthreads();

        // S = Q K^T (4x4 per thread)
        float s[4][4];
#pragma unroll
        for (int i = 0; i < 4; i++)
#pragma unroll
            for (int j = 0; j < 4; j++) s[i][j] = 0.f;

#pragma unroll 8
        for (int d = 0; d < 64; d++) {
            float4 qa = *(const float4*)(Qst + d*68 + ty*4);
            float4 kb = *(const float4*)(KPb + d*68 + tx*4);
            float av[4] = {qa.x, qa.y, qa.z, qa.w};
            float bv[4] = {kb.x, kb.y, kb.z, kb.w};
#pragma unroll
            for (int i = 0; i < 4; i++)
#pragma unroll
                for (int j = 0; j < 4; j++)
                    s[i][j] += av[i] * bv[j];
        }

        // scale + temporal bias + causal mask + online softmax update
#pragma unroll
        for (int i = 0; i < 4; i++) {
            int qr = qi0 + ty*4 + i;
            const float* br = biasB + (size_t)qr*Lx + kj0 + tx*4;
            float rm = -1e30f;
#pragma unroll
            for (int j = 0; j < 4; j++) {
                int kc = kj0 + tx*4 + j;
                float v = s[i][j]*0.125f + br[j];
                if (kc > qr) v = -1e30f;
                s[i][j] = v;
                rm = fmaxf(rm, v);
            }
            rm = fmaxf(rm, __shfl_xor_sync(0xffffffffu, rm, 1));
            rm = fmaxf(rm, __shfl_xor_sync(0xffffffffu, rm, 2));
            rm = fmaxf(rm, __shfl_xor_sync(0xffffffffu, rm, 4));
            rm = fmaxf(rm, __shfl_xor_sync(0xffffffffu, rm, 8));
            float mn = fmaxf(m_i[i], rm);
            float sc = __expf(m_i[i] - mn);
            m_i[i] = mn;
            float rs = 0.f;
#pragma unroll
            for (int j = 0; j < 4; j++) {
                float p = __expf(s[i][j] - mn);
                s[i][j] = p;
                rs += p;
            }
            rs += __shfl_xor_sync(0xffffffffu, rs, 1);
            rs += __shfl_xor_sync(0xffffffffu, rs, 2);
            rs += __shfl_xor_sync(0xffffffffu, rs, 4);
            rs += __shfl_xor_sync(0xffffffffu, rs, 8);
            l_i[i] = l_i[i]*sc + rs;
#pragma unroll
            for (int j = 0; j < 4; j++) O[i][j] *= sc;
        }

        __syncthreads();   // all S-phase reads of KPb complete
#pragma unroll
        for (int i = 0; i < 4; i++)
#pragma unroll
            for (int j = 0; j < 4; j++)
                KPb[(ty*4+i)*68 + tx*4 + j] = s[i][j];
        __syncthreads();

        // O += P @ V
#pragma unroll 8
        for (int k = 0; k < 64; k++) {
            float4 vv = *(const float4*)(Vs + k*64 + tx*4);
#pragma unroll
            for (int i = 0; i < 4; i++) {
                float p = KPb[(ty*4+i)*68 + k];
                O[i][0] += p * vv.x;
                O[i][1] += p * vv.y;
                O[i][2] += p * vv.z;
                O[i][3] += p * vv.w;
            }
        }
    }

    // normalize + write [B,L,H*DK]
#pragma unroll
    for (int i = 0; i < 4; i++) {
        float inv = 1.0f / l_i[i];
        int qr = qi0 + ty*4 + i;
        float4 o4 = make_float4(O[i][0]*inv, O[i][1]*inv, O[i][2]*inv, O[i][3]*inv);
        *(float4*)(g_attn + ((size_t)b*Lx + qr)*Dx + h*DKx + tx*4) = o4;
    }
}

// ---------------- launch ----------------
extern "C" void kernel_launch(void* const* d_in, const int* in_sizes, int n_in,
                              void* d_out, int out_size)
{
    const float* x   = (const float*)d_in[0];
    const float* ts  = (const float*)d_in[1];
    // d_in[2] decay_values, d_in[3] pad_mask: unused by the reference semantics
    const float* Wq  = (const float*)d_in[4];
    const float* bq  = (const float*)d_in[5];
    const float* Wk  = (const float*)d_in[6];
    const float* bk  = (const float*)d_in[7];
    const float* Wv  = (const float*)d_in[8];
    const float* bv  = (const float*)d_in[9];
    const float* Wo  = (const float*)d_in[10];
    const float* bo  = (const float*)d_in[11];
    const float* lam = (const float*)d_in[12];
    float* out = (float*)d_out;

    k_denom<<<1, 1>>>(ts, lam);
    k_bias<<<(Bx*Lx*Lx)/256, 256>>>(ts);

    // Q/K/V projections in one launch (z selects weight set)
    k_gemm<true><<<dim3(8, 32, 3), 256>>>(x, Wq, bq, Wk, bk, Wv, bv, nullptr);

    // flash attention: 52?200... dynamic smem = (2*64*68 + 64*64)*4 = 51200 B
    cudaFuncSetAttribute(k_attn, cudaFuncAttributeMaxDynamicSharedMemorySize, 51200);
    k_attn<<<dim3(Lx/64, BHx), 256, 51200>>>();

    // output projection
    k_gemm<false><<<dim3(8, 32, 1), 256>>>(nullptr, Wo, bo, nullptr, nullptr, nullptr, nullptr, out);
}

// round 2
// speedup vs baseline: 1.0099x; 1.0099x over previous
#include <cuda_runtime.h>
#include <math.h>

// Problem constants
#define Bx  2
#define Lx  2048
#define Dx  1024
#define Hx  16
#define DKx 64
#define BHx (Bx*Hx)

// ---------------- device scratch (no allocations allowed) ----------------
__device__ float g_Q[(size_t)BHx*Lx*DKx];      // [B,H,L,DK]
__device__ float g_K[(size_t)BHx*Lx*DKx];
__device__ float g_V[(size_t)BHx*Lx*DKx];
__device__ float g_attn[(size_t)Bx*Lx*Dx];     // [B,L,H*DK]
__device__ float g_bias[(size_t)Bx*Lx*Lx];     // -|lam|*log1p(|ti-tj|/denom)
__device__ float g_scal[2];                    // [0]=1/denom, [1]=-|lam|

// ---------------- denom + lam scalars ----------------
__global__ void k_denom(const float* __restrict__ ts, const float* __restrict__ lam)
{
    // timestamps are sorted ascending along L, so max |ti-tj| per batch = t[L-1]-t[0]
    float m = 1.0f;
    for (int b = 0; b < Bx; b++) {
        float d = ts[b*Lx + (Lx-1)] - ts[b*Lx + 0];
        m = fmaxf(m, d);
    }
    g_scal[0] = 1.0f / m;
    g_scal[1] = -fabsf(lam[0]);
}

// ---------------- temporal bias precompute ----------------
__global__ __launch_bounds__(256) void k_bias(const float* __restrict__ ts)
{
    long idx = (long)blockIdx.x * 256 + threadIdx.x;   // over B*L*L, exact multiple
    int  j = (int)(idx & (Lx-1));
    long t = idx >> 11;
    int  i = (int)(t & (Lx-1));
    int  b = (int)(t >> 11);
    float d = fabsf(ts[b*Lx + i] - ts[b*Lx + j]);
    g_bias[idx] = g_scal[1] * log1pf(d * g_scal[0]);
}

// ---------------- tiled fp32 GEMM:  out[m,n] = sum_k A[m,k]*W[n,k] + bias[n] ----------------
// BM=BN=128, BK=16, 256 threads, 8x8 microtiles.
// SCATTER=true : three outputs (Q,K,V) selected by blockIdx.z, written as [B,H,L,DK]
// SCATTER=false: A = g_attn, plain row-major write to outp
template<bool SCATTER>
__global__ __launch_bounds__(256) void k_gemm(
    const float* __restrict__ Ain,
    const float* __restrict__ W0, const float* __restrict__ b0,
    const float* __restrict__ W1, const float* __restrict__ b1,
    const float* __restrict__ W2, const float* __restrict__ b2,
    float* __restrict__ outp)
{
    __shared__ float As[16][132];
    __shared__ float Bs[16][132];

    const float* A;
    const float* W;
    const float* bias;
    float* out;
    if (SCATTER) {
        A = Ain;
        if (blockIdx.z == 0)      { W = W0; bias = b0; out = g_Q; }
        else if (blockIdx.z == 1) { W = W1; bias = b1; out = g_K; }
        else                      { W = W2; bias = b2; out = g_V; }
    } else {
        A = g_attn; W = W0; bias = b0; out = outp;
    }

    const int tid = threadIdx.x;
    const int ty = tid >> 4, tx = tid & 15;
    const int m0 = blockIdx.y * 128, n0 = blockIdx.x * 128;

    float acc[8][8];
#pragma unroll
    for (int i = 0; i < 8; i++)
#pragma unroll
        for (int j = 0; j < 8; j++) acc[i][j] = 0.f;

    for (int k0 = 0; k0 < Dx; k0 += 16) {
#pragma unroll
        for (int t = 0; t < 2; t++) {
            int idx = tid + t*256;            // 0..511
            int row = idx >> 2, q = idx & 3;
            float4 va = *(const float4*)(A + (size_t)(m0+row)*Dx + k0 + q*4);
            As[q*4+0][row] = va.x; As[q*4+1][row] = va.y;
            As[q*4+2][row] = va.z; As[q*4+3][row] = va.w;
            float4 vb = *(const float4*)(W + (size_t)(n0+row)*Dx + k0 + q*4);
            Bs[q*4+0][row] = vb.x; Bs[q*4+1][row] = vb.y;
            Bs[q*4+2][row] = vb.z; Bs[q*4+3][row] = vb.w;
        }
        __syncthreads();
#pragma unroll
        for (int kk = 0; kk < 16; kk++) {
            float a[8], bb[8];
            *(float4*)&a[0]  = *(const float4*)&As[kk][ty*8];
            *(float4*)&a[4]  = *(const float4*)&As[kk][ty*8+4];
            *(float4*)&bb[0] = *(const float4*)&Bs[kk][tx*8];
            *(float4*)&bb[4] = *(const float4*)&Bs[kk][tx*8+4];
#pragma unroll
            for (int i = 0; i < 8; i++)
#pragma unroll
                for (int j = 0; j < 8; j++)
                    acc[i][j] += a[i] * bb[j];
        }
        __syncthreads();
    }

#pragma unroll
    for (int i = 0; i < 8; i++) {
        int m = m0 + ty*8 + i;
        int b_ = m >> 11;          // / L
        int l  = m & (Lx-1);
#pragma unroll
        for (int j = 0; j < 8; j++) {
            int n = n0 + tx*8 + j;
            float v = acc[i][j] + bias[n];
            if (SCATTER) {
                int h = n >> 6, dk = n & 63;
                out[(((size_t)b_*Hx + h)*Lx + l)*DKx + dk] = v;
            } else {
                out[(size_t)m*Dx + n] = v;
            }
        }
    }
}

// ---------------- fp32 causal flash attention with temporal bias ----------------
// One block handles 64 query rows of one (b,h). 256 threads (16x16), each owns a
// 4x4 tile of S and of O (DK=64 columns map to the same 16x4 column split).
__global__ __launch_bounds__(256) void k_attn()
{
    extern __shared__ float sm[];
    float* Qst = sm;               // [64 d][68] transposed Q tile
    float* KPb = sm + 64*68;       // K transposed [d][68], reused as P [r][68]
    float* Vs  = sm + 2*64*68;     // [64 k][64] natural

    const int tid = threadIdx.x;
    const int ty = tid >> 4, tx = tid & 15;
    const int qt = blockIdx.x;
    const int bh = blockIdx.y;
    const int b  = bh >> 4, h = bh & 15;
    const int qi0 = qt * 64;

    const float* Qg = g_Q + (size_t)bh*Lx*DKx + (size_t)qi0*DKx;
    const float* Kg = g_K + (size_t)bh*Lx*DKx;
    const float* Vg = g_V + (size_t)bh*Lx*DKx;
    const float* biasB = g_bias + (size_t)b*Lx*Lx;

    // load Q tile transposed: Qst[d][r]
#pragma unroll
    for (int t = 0; t < 4; t++) {
        int idx = tid + t*256;          // 0..1023
        int r = idx >> 4, d4 = idx & 15;
        float4 v = *(const float4*)(Qg + (size_t)r*DKx + d4*4);
        Qst[(d4*4+0)*68 + r] = v.x;
        Qst[(d4*4+1)*68 + r] = v.y;
        Qst[(d4*4+2)*68 + r] = v.z;
        Qst[(d4*4+3)*68 + r] = v.w;
    }

    float m_i[4], l_i[4], O[4][4];
#pragma unroll
    for (int i = 0; i < 4; i++) {
        m_i[i] = -1e30f; l_i[i] = 0.f;
#pragma unroll
        for (int j = 0; j < 4; j++) O[i][j] = 0.f;
    }

    for (int jt = 0; jt <= qt; jt++) {
        const int kj0 = jt * 64;
        __syncthreads();   // protect KPb/Vs from previous iteration's readers
#pragma unroll
        for (int t = 0; t < 4; t++) {
            int idx = tid + t*256;
            int r = idx >> 4, d4 = idx & 15;
            float4 kv = *(const float4*)(Kg + (size_t)(kj0+r)*DKx + d4*4);
            KPb[(d4*4+0)*68 + r] = kv.x;
            KPb[(d4*4+1)*68 + r] = kv.y;
            KPb[(d4*4+2)*68 + r] = kv.z;
            KPb[(d4*4+3)*68 + r] = kv.w;
            float4 vv = *(const float4*)(Vg + (size_t)(kj0+r)*DKx + d4*4);
            *(float4*)(Vs + r*64 + d4*4) = vv;
        }
        __syncthreads();

        // S = Q K^T (4x4 per thread)
        float s[4][4];
#pragma unroll
        for (int i = 0; i < 4; i++)
#pragma unroll
            for (int j = 0; j < 4; j++) s[i][j] = 0.f;

#pragma unroll 8
        for (int d = 0; d < 64; d++) {
            float4 qa = *(const float4*)(Qst + d*68 + ty*4);
            float4 kb = *(const float4*)(KPb + d*68 + tx*4);
            float av[4] = {qa.x, qa.y, qa.z, qa.w};
            float bv[4] = {kb.x, kb.y, kb.z, kb.w};
#pragma unroll
            for (int i = 0; i < 4; i++)
#pragma unroll
                for (int j = 0; j < 4; j++)
                    s[i][j] += av[i] * bv[j];
        }

        // scale + temporal bias + causal mask + online softmax update
#pragma unroll
        for (int i = 0; i < 4; i++) {
            int qr = qi0 + ty*4 + i;
            const float* br = biasB + (size_t)qr*Lx + kj0 + tx*4;
            float rm = -1e30f;
#pragma unroll
            for (int j = 0; j < 4; j++) {
                int kc = kj0 + tx*4 + j;
                float v = s[i][j]*0.125f + br[j];
                if (kc > qr) v = -1e30f;
                s[i][j] = v;
                rm = fmaxf(rm, v);
            }
            rm = fmaxf(rm, __shfl_xor_sync(0xffffffffu, rm, 1));
            rm = fmaxf(rm, __shfl_xor_sync(0xffffffffu, rm, 2));
            rm = fmaxf(rm, __shfl_xor_sync(0xffffffffu, rm, 4));
            rm = fmaxf(rm, __shfl_xor_sync(0xffffffffu, rm, 8));
            float mn = fmaxf(m_i[i], rm);
            float sc = __expf(m_i[i] - mn);
            m_i[i] = mn;
            float rs = 0.f;
#pragma unroll
            for (int j = 0; j < 4; j++) {
                float p = __expf(s[i][j] - mn);
                s[i][j] = p;
                rs += p;
            }
            rs += __shfl_xor_sync(0xffffffffu, rs, 1);
            rs += __shfl_xor_sync(0xffffffffu, rs, 2);
            rs += __shfl_xor_sync(0xffffffffu, rs, 4);
            rs += __shfl_xor_sync(0xffffffffu, rs, 8);
            l_i[i] = l_i[i]*sc + rs;
#pragma unroll
            for (int j = 0; j < 4; j++) O[i][j] *= sc;
        }

        __syncthreads();   // all S-phase reads of KPb complete
#pragma unroll
        for (int i = 0; i < 4; i++)
#pragma unroll
            for (int j = 0; j < 4; j++)
                KPb[(ty*4+i)*68 + tx*4 + j] = s[i][j];
        __syncthreads();

        // O += P @ V
#pragma unroll 8
        for (int k = 0; k < 64; k++) {
            float4 vv = *(const float4*)(Vs + k*64 + tx*4);
#pragma unroll
            for (int i = 0; i < 4; i++) {
                float p = KPb[(ty*4+i)*68 + k];
                O[i][0] += p * vv.x;
                O[i][1] += p * vv.y;
                O[i][2] += p * vv.z;
                O[i][3] += p * vv.w;
            }
        }
    }

    // normalize + write [B,L,H*DK]
#pragma unroll
    for (int i = 0; i < 4; i++) {
        float inv = 1.0f / l_i[i];
        int qr = qi0 + ty*4 + i;
        float4 o4 = make_float4(O[i][0]*inv, O[i][1]*inv, O[i][2]*inv, O[i][3]*inv);
        *(float4*)(g_attn + ((size_t)b*Lx + qr)*Dx + h*DKx + tx*4) = o4;
    }
}

// ---------------- launch ----------------
extern "C" void kernel_launch(void* const* d_in, const int* in_sizes, int n_in,
                              void* d_out, int out_size)
{
    const float* x   = (const float*)d_in[0];
    const float* ts  = (const float*)d_in[1];
    // d_in[2] decay_values, d_in[3] pad_mask: unused by the reference semantics
    const float* Wq  = (const float*)d_in[4];
    const float* bq  = (const float*)d_in[5];
    const float* Wk  = (const float*)d_in[6];
    const float* bk  = (const float*)d_in[7];
    const float* Wv  = (const float*)d_in[8];
    const float* bv  = (const float*)d_in[9];
    const float* Wo  = (const float*)d_in[10];
    const float* bo  = (const float*)d_in[11];
    const float* lam = (const float*)d_in[12];
    float* out = (float*)d_out;

    k_denom<<<1, 1>>>(ts, lam);
    k_bias<<<(Bx*Lx*Lx)/256, 256>>>(ts);

    // Q/K/V projections in one launch (z selects weight set)
    k_gemm<true><<<dim3(8, 32, 3), 256>>>(x, Wq, bq, Wk, bk, Wv, bv, nullptr);

    // flash attention: 52?200... dynamic smem = (2*64*68 + 64*64)*4 = 51200 B
    cudaFuncSetAttribute(k_attn, cudaFuncAttributeMaxDynamicSharedMemorySize, 51200);
    k_attn<<<dim3(Lx/64, BHx), 256, 51200>>>();

    // output projection
    k_gemm<false><<<dim3(8, 32, 1), 256>>>(nullptr, Wo, bo, nullptr, nullptr, nullptr, nullptr, out);
}

// round 4
// speedup vs baseline: 1.4819x; 1.4673x over previous
#include <cuda_runtime.h>
#include <math.h>
#include <stdint.h>

// Problem constants
#define Bx  2
#define Lx  2048
#define Dx  1024
#define Hx  16
#define DKx 64
#define BHx (Bx*Hx)

// ---------------- device scratch (no allocations allowed) ----------------
__device__ float g_Q[(size_t)BHx*Lx*DKx];      // [B,H,L,DK]
__device__ float g_K[(size_t)BHx*Lx*DKx];
__device__ float g_V[(size_t)BHx*Lx*DKx];
__device__ float g_attn[(size_t)Bx*Lx*Dx];     // [B,L,H*DK]
__device__ float g_bias[(size_t)Bx*Lx*Lx];     // -|lam|*log1p(|ti-tj|/denom)
__device__ float g_scal[2];                    // [0]=1/denom, [1]=-|lam|

// ---------------- helpers ----------------
__device__ __forceinline__ uint32_t to_tf32(float x) {
    uint32_t r;
    asm("cvt.rna.tf32.f32 %0, %1;" : "=r"(r) : "f"(x));
    return r;
}

__device__ __forceinline__ void mma16n8k8(float* c, const uint32_t* a, const uint32_t* b) {
    asm volatile(
        "mma.sync.aligned.m16n8k8.row.col.f32.tf32.tf32.f32 "
        "{%0,%1,%2,%3}, {%4,%5,%6,%7}, {%8,%9}, {%0,%1,%2,%3};"
        : "+f"(c[0]), "+f"(c[1]), "+f"(c[2]), "+f"(c[3])
        : "r"(a[0]), "r"(a[1]), "r"(a[2]), "r"(a[3]), "r"(b[0]), "r"(b[1]));
}

// Fast exp on the FMA pipe (arg <= 0 expected; clamps below -80 -> ~0).
// rel err ~2e-6; avoids the MUFU EX2 throughput wall.
__device__ __forceinline__ float fexp(float x) {
    x = fmaxf(x, -80.0f);
    float z = fmaf(x, 1.4426950408889634f, 12582912.0f);   // round(x*log2e) in mantissa
    int   ni = __float_as_int(z) - 0x4B400000;             // integer n
    float fn = z - 12582912.0f;
    float f  = fmaf(x, 1.4426950408889634f, -fn);          // frac in [-0.5, 0.5]
    float p = 0.0013333558f;
    p = fmaf(p, f, 0.0096181291f);
    p = fmaf(p, f, 0.0555041087f);
    p = fmaf(p, f, 0.2402265069f);
    p = fmaf(p, f, 0.6931471806f);
    p = fmaf(p, f, 1.0f);
    return __int_as_float(__float_as_int(p) + (ni << 23));
}

// ---------------- denom + lam scalars ----------------
__global__ void k_denom(const float* __restrict__ ts, const float* __restrict__ lam)
{
    float m = 1.0f;
    for (int b = 0; b < Bx; b++) {
        float d = ts[b*Lx + (Lx-1)] - ts[b*Lx + 0];
        m = fmaxf(m, d);
    }
    g_scal[0] = 1.0f / m;
    g_scal[1] = -fabsf(lam[0]);
}

// ---------------- temporal bias precompute ----------------
__global__ __launch_bounds__(256) void k_bias(const float* __restrict__ ts)
{
    long idx = (long)blockIdx.x * 256 + threadIdx.x;
    int  j = (int)(idx & (Lx-1));
    long t = idx >> 11;
    int  i = (int)(t & (Lx-1));
    int  b = (int)(t >> 11);
    float d = fabsf(ts[b*Lx + i] - ts[b*Lx + j]);
    g_bias[idx] = g_scal[1] * log1pf(d * g_scal[0]);
}

// ---------------- tf32 mma.sync GEMM: out[m,n] = sum_k A[m,k]*W[n,k] + bias[n] ----
// BM=128, BN=256, BK=16. 256 threads = 8 warps (2m x 4n), warp tile 64x64.
// Double-buffered smem with register prefetch; inputs rounded to tf32 at staging.
#define BM 128
#define BN 256
#define BK 16
#define LDA 20                      // padded row stride (floats) — conflict-free frags
#define STG_U32 ((BM + BN) * LDA)   // u32 per stage
#define GEMM_SMEM (2 * STG_U32 * 4)

template<bool SCATTER>
__global__ __launch_bounds__(256, 1) void k_gemm_mma(
    const float* __restrict__ Ain,
    const float* __restrict__ W0, const float* __restrict__ b0,
    const float* __restrict__ W1, const float* __restrict__ b1,
    const float* __restrict__ W2, const float* __restrict__ b2,
    float* __restrict__ outp)
{
    extern __shared__ uint32_t sm4[];

    const float* A;
    const float* W;
    const float* bias;
    float* out;
    if (SCATTER) {
        A = Ain;
        if (blockIdx.z == 0)      { W = W0; bias = b0; out = g_Q; }
        else if (blockIdx.z == 1) { W = W1; bias = b1; out = g_K; }
        else                      { W = W2; bias = b2; out = g_V; }
    } else {
        A = g_attn; W = W0; bias = b0; out = outp;
    }

    const int tid = threadIdx.x;
    const int wid = tid >> 5;
    const int lane = tid & 31;
    const int wm = wid >> 2;          // 0..1
    const int wn = wid & 3;           // 0..3
    const int lr = lane >> 2;         // 0..7
    const int lc = lane & 3;          // 0..3

    const int m0 = blockIdx.y * BM;
    const int n0 = blockIdx.x * BN;

    float c[4][8][4];
#pragma unroll
    for (int i = 0; i < 4; i++)
#pragma unroll
        for (int j = 0; j < 8; j++)
#pragma unroll
            for (int q = 0; q < 4; q++) c[i][j][q] = 0.f;

    // staging register buffers
    float4 pa[2], pb[4];

    auto gload = [&](int k0) {
#pragma unroll
        for (int t = 0; t < 2; t++) {
            int i = tid + t * 256;            // 0..511
            int row = i >> 2, q = i & 3;
            pa[t] = *(const float4*)(A + (size_t)(m0 + row) * Dx + k0 + q * 4);
        }
#pragma unroll
        for (int t = 0; t < 4; t++) {
            int i = tid + t * 256;            // 0..1023
            int row = i >> 2, q = i & 3;
            pb[t] = *(const float4*)(W + (size_t)(n0 + row) * Dx + k0 + q * 4);
        }
    };
    auto sstore = [&](int buf) {
        uint32_t* As = sm4 + buf * STG_U32;
        uint32_t* Bs = As + BM * LDA;
#pragma unroll
        for (int t = 0; t < 2; t++) {
            int i = tid + t * 256;
            int row = i >> 2, q = i & 3;
            uint32_t* p = As + row * LDA + q * 4;
            p[0] = to_tf32(pa[t].x); p[1] = to_tf32(pa[t].y);
            p[2] = to_tf32(pa[t].z); p[3] = to_tf32(pa[t].w);
        }
#pragma unroll
        for (int t = 0; t < 4; t++) {
            int i = tid + t * 256;
            int row = i >> 2, q = i & 3;
            uint32_t* p = Bs + row * LDA + q * 4;
            p[0] = to_tf32(pb[t].x); p[1] = to_tf32(pb[t].y);
            p[2] = to_tf32(pb[t].z); p[3] = to_tf32(pb[t].w);
        }
    };

    gload(0);
    sstore(0);
    __syncthreads();

    const int NITER = Dx / BK;
    for (int it = 0; it < NITER; ++it) {
        const int buf = it & 1;
        if (it + 1 < NITER) gload((it + 1) * BK);

        const uint32_t* As = sm4 + buf * STG_U32;
        const uint32_t* Bs = As + BM * LDA;
        const int mbase = wm * 64;
        const int nbase = wn * 64;
#pragma unroll
        for (int ks = 0; ks < 2; ks++) {
            const int k = ks * 8;
            uint32_t af[4][4], bf[8][2];
#pragma unroll
            for (int mt = 0; mt < 4; mt++) {
                const uint32_t* p = As + (mbase + mt * 16 + lr) * LDA + k + lc;
                af[mt][0] = p[0];
                af[mt][2] = p[4];
                af[mt][1] = p[8 * LDA];
                af[mt][3] = p[8 * LDA + 4];
            }
#pragma unroll
            for (int nt = 0; nt < 8; nt++) {
                const uint32_t* p = Bs + (nbase + nt * 8 + lr) * LDA + k + lc;
                bf[nt][0] = p[0];
                bf[nt][1] = p[4];
            }
#pragma unroll
            for (int mt = 0; mt < 4; mt++)
#pragma unroll
                for (int nt = 0; nt < 8; nt++)
                    mma16n8k8(c[mt][nt], af[mt], bf[nt]);
        }
        __syncthreads();
        if (it + 1 < NITER) {
            sstore((it + 1) & 1);
            __syncthreads();
        }
    }

    // epilogue: add bias, store (optionally scattered to [B,H,L,DK])
#pragma unroll
    for (int mt = 0; mt < 4; mt++) {
        const int mA = m0 + wm * 64 + mt * 16 + lr;
        const int mB = mA + 8;
#pragma unroll
        for (int nt = 0; nt < 8; nt++) {
            const int n = n0 + wn * 64 + nt * 8 + 2 * lc;
            const float bn0 = bias[n], bn1 = bias[n + 1];
            float2 v0 = make_float2(c[mt][nt][0] + bn0, c[mt][nt][1] + bn1);
            float2 v1 = make_float2(c[mt][nt][2] + bn0, c[mt][nt][3] + bn1);
            if (SCATTER) {
                const int h = n >> 6, dk = n & 63;
                const int bA = mA >> 11, lA = mA & (Lx - 1);
                const int bB = mB >> 11, lB = mB & (Lx - 1);
                *(float2*)(out + (((size_t)bA*Hx + h)*Lx + lA)*DKx + dk) = v0;
                *(float2*)(out + (((size_t)bB*Hx + h)*Lx + lB)*DKx + dk) = v1;
            } else {
                *(float2*)(out + (size_t)mA * Dx + n) = v0;
                *(float2*)(out + (size_t)mB * Dx + n) = v1;
            }
        }
    }
}

// ---------------- fp32 causal flash attention with temporal bias ----------------
__global__ __launch_bounds__(256) void k_attn()
{
    extern __shared__ float sm[];
    float* Qst = sm;               // [64 d][68] transposed Q tile
    float* KPb = sm + 64*68;       // K transposed [d][68], reused as P [r][68]
    float* Vs  = sm + 2*64*68;     // [64 k][64] natural

    const int tid = threadIdx.x;
    const int ty = tid >> 4, tx = tid & 15;
    const int qt = blockIdx.x;
    const int bh = blockIdx.y;
    const int b  = bh >> 4, h = bh & 15;
    const int qi0 = qt * 64;

    const float* Qg = g_Q + (size_t)bh*Lx*DKx + (size_t)qi0*DKx;
    const float* Kg = g_K + (size_t)bh*Lx*DKx;
    const float* Vg = g_V + (size_t)bh*Lx*DKx;
    const float* biasB = g_bias + (size_t)b*Lx*Lx;

#pragma unroll
    for (int t = 0; t < 4; t++) {
        int idx = tid + t*256;
        int r = idx >> 4, d4 = idx & 15;
        float4 v = *(const float4*)(Qg + (size_t)r*DKx + d4*4);
        Qst[(d4*4+0)*68 + r] = v.x;
        Qst[(d4*4+1)*68 + r] = v.y;
        Qst[(d4*4+2)*68 + r] = v.z;
        Qst[(d4*4+3)*68 + r] = v.w;
    }

    float m_i[4], l_i[4], O[4][4];
#pragma unroll
    for (int i = 0; i < 4; i++) {
        m_i[i] = -1e30f; l_i[i] = 0.f;
#pragma unroll
        for (int j = 0; j < 4; j++) O[i][j] = 0.f;
    }

    for (int jt = 0; jt <= qt; jt++) {
        const int kj0 = jt * 64;
        __syncthreads();
#pragma unroll
        for (int t = 0; t < 4; t++) {
            int idx = tid + t*256;
            int r = idx >> 4, d4 = idx & 15;
            float4 kv = *(const float4*)(Kg + (size_t)(kj0+r)*DKx + d4*4);
            KPb[(d4*4+0)*68 + r] = kv.x;
            KPb[(d4*4+1)*68 + r] = kv.y;
            KPb[(d4*4+2)*68 + r] = kv.z;
            KPb[(d4*4+3)*68 + r] = kv.w;
            float4 vv = *(const float4*)(Vg + (size_t)(kj0+r)*DKx + d4*4);
            *(float4*)(Vs + r*64 + d4*4) = vv;
        }
        __syncthreads();

        float s[4][4];
#pragma unroll
        for (int i = 0; i < 4; i++)
#pragma unroll
            for (int j = 0; j < 4; j++) s[i][j] = 0.f;

#pragma unroll 8
        for (int d = 0; d < 64; d++) {
            float4 qa = *(const float4*)(Qst + d*68 + ty*4);
            float4 kb = *(const float4*)(KPb + d*68 + tx*4);
            float av[4] = {qa.x, qa.y, qa.z, qa.w};
            float bv[4] = {kb.x, kb.y, kb.z, kb.w};
#pragma unroll
            for (int i = 0; i < 4; i++)
#pragma unroll
                for (int j = 0; j < 4; j++)
                    s[i][j] += av[i] * bv[j];
        }

#pragma unroll
        for (int i = 0; i < 4; i++) {
            int qr = qi0 + ty*4 + i;
            const float* br = biasB + (size_t)qr*Lx + kj0 + tx*4;
            float rm = -1e30f;
#pragma unroll
            for (int j = 0; j < 4; j++) {
                int kc = kj0 + tx*4 + j;
                float v = s[i][j]*0.125f + br[j];
                if (kc > qr) v = -1e30f;
                s[i][j] = v;
                rm = fmaxf(rm, v);
            }
            rm = fmaxf(rm, __shfl_xor_sync(0xffffffffu, rm, 1));
            rm = fmaxf(rm, __shfl_xor_sync(0xffffffffu, rm, 2));
            rm = fmaxf(rm, __shfl_xor_sync(0xffffffffu, rm, 4));
            rm = fmaxf(rm, __shfl_xor_sync(0xffffffffu, rm, 8));
            float mn = fmaxf(m_i[i], rm);
            float sc = fexp(m_i[i] - mn);
            m_i[i] = mn;
            float rs = 0.f;
#pragma unroll
            for (int j = 0; j < 4; j++) {
                float p = fexp(s[i][j] - mn);
                s[i][j] = p;
                rs += p;
            }
            rs += __shfl_xor_sync(0xffffffffu, rs, 1);
            rs += __shfl_xor_sync(0xffffffffu, rs, 2);
            rs += __shfl_xor_sync(0xffffffffu, rs, 4);
            rs += __shfl_xor_sync(0xffffffffu, rs, 8);
            l_i[i] = l_i[i]*sc + rs;
#pragma unroll
            for (int j = 0; j < 4; j++) O[i][j] *= sc;
        }

        __syncthreads();
#pragma unroll
        for (int i = 0; i < 4; i++)
#pragma unroll
            for (int j = 0; j < 4; j++)
                KPb[(ty*4+i)*68 + tx*4 + j] = s[i][j];
        __syncthreads();

#pragma unroll 8
        for (int k = 0; k < 64; k++) {
            float4 vv = *(const float4*)(Vs + k*64 + tx*4);
#pragma unroll
            for (int i = 0; i < 4; i++) {
                float p = KPb[(ty*4+i)*68 + k];
                O[i][0] += p * vv.x;
                O[i][1] += p * vv.y;
                O[i][2] += p * vv.z;
                O[i][3] += p * vv.w;
            }
        }
    }

#pragma unroll
    for (int i = 0; i < 4; i++) {
        float inv = 1.0f / l_i[i];
        int qr = qi0 + ty*4 + i;
        float4 o4 = make_float4(O[i][0]*inv, O[i][1]*inv, O[i][2]*inv, O[i][3]*inv);
        *(float4*)(g_attn + ((size_t)b*Lx + qr)*Dx + h*DKx + tx*4) = o4;
    }
}

// ---------------- launch ----------------
extern "C" void kernel_launch(void* const* d_in, const int* in_sizes, int n_in,
                              void* d_out, int out_size)
{
    const float* x   = (const float*)d_in[0];
    const float* ts  = (const float*)d_in[1];
    const float* Wq  = (const float*)d_in[4];
    const float* bq  = (const float*)d_in[5];
    const float* Wk  = (const float*)d_in[6];
    const float* bk  = (const float*)d_in[7];
    const float* Wv  = (const float*)d_in[8];
    const float* bv  = (const float*)d_in[9];
    const float* Wo  = (const float*)d_in[10];
    const float* bo  = (const float*)d_in[11];
    const float* lam = (const float*)d_in[12];
    float* out = (float*)d_out;

    k_denom<<<1, 1>>>(ts, lam);
    k_bias<<<(Bx*Lx*Lx)/256, 256>>>(ts);

    cudaFuncSetAttribute(k_gemm_mma<true>,  cudaFuncAttributeMaxDynamicSharedMemorySize, GEMM_SMEM);
    cudaFuncSetAttribute(k_gemm_mma<false>, cudaFuncAttributeMaxDynamicSharedMemorySize, GEMM_SMEM);

    // Q/K/V projections: grid (N-tiles=4, M-tiles=32, 3)
    k_gemm_mma<true><<<dim3(Dx/BN, (Bx*Lx)/BM, 3), 256, GEMM_SMEM>>>(
        x, Wq, bq, Wk, bk, Wv, bv, nullptr);

    cudaFuncSetAttribute(k_attn, cudaFuncAttributeMaxDynamicSharedMemorySize, 51200);
    k_attn<<<dim3(Lx/64, BHx), 256, 51200>>>();

    // output projection
    k_gemm_mma<false><<<dim3(Dx/BN, (Bx*Lx)/BM, 1), 256, GEMM_SMEM>>>(
        nullptr, Wo, bo, nullptr, nullptr, nullptr, nullptr, out);
}

// round 5
// speedup vs baseline: 2.2098x; 1.4912x over previous
#include <cuda_runtime.h>
#include <math.h>
#include <stdint.h>

// Problem constants
#define Bx  2
#define Lx  2048
#define Dx  1024
#define Hx  16
#define DKx 64
#define BHx (Bx*Hx)

// ---------------- device scratch (no allocations allowed) ----------------
__device__ float g_Q[(size_t)BHx*Lx*DKx];      // [B,H,L,DK]
__device__ float g_K[(size_t)BHx*Lx*DKx];
__device__ float g_V[(size_t)BHx*Lx*DKx];
__device__ float g_attn[(size_t)Bx*Lx*Dx];     // [B,L,H*DK]
__device__ float g_bias[(size_t)Bx*Lx*Lx];     // -|lam|*log1p(|ti-tj|/denom)
__device__ float g_scal[2];                    // [0]=1/denom, [1]=-|lam|

// ---------------- helpers ----------------
__device__ __forceinline__ uint32_t to_tf32(float x) {
    uint32_t r;
    asm("cvt.rna.tf32.f32 %0, %1;" : "=r"(r) : "f"(x));
    return r;
}
__device__ __forceinline__ void split_tf32(float x, float& hi, float& lo) {
    hi = __uint_as_float(to_tf32(x));
    lo = __uint_as_float(to_tf32(x - hi));
}

__device__ __forceinline__ void mma16n8k8(float* c, const uint32_t* a, const uint32_t* b) {
    asm volatile(
        "mma.sync.aligned.m16n8k8.row.col.f32.tf32.tf32.f32 "
        "{%0,%1,%2,%3}, {%4,%5,%6,%7}, {%8,%9}, {%0,%1,%2,%3};"
        : "+f"(c[0]), "+f"(c[1]), "+f"(c[2]), "+f"(c[3])
        : "r"(a[0]), "r"(a[1]), "r"(a[2]), "r"(a[3]), "r"(b[0]), "r"(b[1]));
}

// Fast exp on the FMA pipe (clamps below -80 -> ~0).
__device__ __forceinline__ float fexp(float x) {
    x = fmaxf(x, -80.0f);
    float z = fmaf(x, 1.4426950408889634f, 12582912.0f);
    int   ni = __float_as_int(z) - 0x4B400000;
    float fn = z - 12582912.0f;
    float f  = fmaf(x, 1.4426950408889634f, -fn);
    float p = 0.0013333558f;
    p = fmaf(p, f, 0.0096181291f);
    p = fmaf(p, f, 0.0555041087f);
    p = fmaf(p, f, 0.2402265069f);
    p = fmaf(p, f, 0.6931471806f);
    p = fmaf(p, f, 1.0f);
    return __int_as_float(__float_as_int(p) + (ni << 23));
}

// ---------------- denom + lam scalars ----------------
__global__ void k_denom(const float* __restrict__ ts, const float* __restrict__ lam)
{
    float m = 1.0f;
    for (int b = 0; b < Bx; b++) {
        float d = ts[b*Lx + (Lx-1)] - ts[b*Lx + 0];
        m = fmaxf(m, d);
    }
    g_scal[0] = 1.0f / m;
    g_scal[1] = -fabsf(lam[0]);
}

// ---------------- temporal bias precompute ----------------
__global__ __launch_bounds__(256) void k_bias(const float* __restrict__ ts)
{
    long idx = (long)blockIdx.x * 256 + threadIdx.x;
    int  j = (int)(idx & (Lx-1));
    long t = idx >> 11;
    int  i = (int)(t & (Lx-1));
    int  b = (int)(t >> 11);
    float d = fabsf(ts[b*Lx + i] - ts[b*Lx + j]);
    g_bias[idx] = g_scal[1] * log1pf(d * g_scal[0]);
}

// ---------------- tf32 mma.sync GEMM (unchanged from R3) ----------------
#define BM 128
#define BN 256
#define BK 16
#define LDA 20
#define STG_U32 ((BM + BN) * LDA)
#define GEMM_SMEM (2 * STG_U32 * 4)

template<bool SCATTER>
__global__ __launch_bounds__(256, 1) void k_gemm_mma(
    const float* __restrict__ Ain,
    const float* __restrict__ W0, const float* __restrict__ b0,
    const float* __restrict__ W1, const float* __restrict__ b1,
    const float* __restrict__ W2, const float* __restrict__ b2,
    float* __restrict__ outp)
{
    extern __shared__ uint32_t sm4[];

    const float* A;
    const float* W;
    const float* bias;
    float* out;
    if (SCATTER) {
        A = Ain;
        if (blockIdx.z == 0)      { W = W0; bias = b0; out = g_Q; }
        else if (blockIdx.z == 1) { W = W1; bias = b1; out = g_K; }
        else                      { W = W2; bias = b2; out = g_V; }
    } else {
        A = g_attn; W = W0; bias = b0; out = outp;
    }

    const int tid = threadIdx.x;
    const int wid = tid >> 5;
    const int lane = tid & 31;
    const int wm = wid >> 2;
    const int wn = wid & 3;
    const int lr = lane >> 2;
    const int lc = lane & 3;

    const int m0 = blockIdx.y * BM;
    const int n0 = blockIdx.x * BN;

    float c[4][8][4];
#pragma unroll
    for (int i = 0; i < 4; i++)
#pragma unroll
        for (int j = 0; j < 8; j++)
#pragma unroll
            for (int q = 0; q < 4; q++) c[i][j][q] = 0.f;

    float4 pa[2], pb[4];

    auto gload = [&](int k0) {
#pragma unroll
        for (int t = 0; t < 2; t++) {
            int i = tid + t * 256;
            int row = i >> 2, q = i & 3;
            pa[t] = *(const float4*)(A + (size_t)(m0 + row) * Dx + k0 + q * 4);
        }
#pragma unroll
        for (int t = 0; t < 4; t++) {
            int i = tid + t * 256;
            int row = i >> 2, q = i & 3;
            pb[t] = *(const float4*)(W + (size_t)(n0 + row) * Dx + k0 + q * 4);
        }
    };
    auto sstore = [&](int buf) {
        uint32_t* As = sm4 + buf * STG_U32;
        uint32_t* Bs = As + BM * LDA;
#pragma unroll
        for (int t = 0; t < 2; t++) {
            int i = tid + t * 256;
            int row = i >> 2, q = i & 3;
            uint32_t* p = As + row * LDA + q * 4;
            p[0] = to_tf32(pa[t].x); p[1] = to_tf32(pa[t].y);
            p[2] = to_tf32(pa[t].z); p[3] = to_tf32(pa[t].w);
        }
#pragma unroll
        for (int t = 0; t < 4; t++) {
            int i = tid + t * 256;
            int row = i >> 2, q = i & 3;
            uint32_t* p = Bs + row * LDA + q * 4;
            p[0] = to_tf32(pb[t].x); p[1] = to_tf32(pb[t].y);
            p[2] = to_tf32(pb[t].z); p[3] = to_tf32(pb[t].w);
        }
    };

    gload(0);
    sstore(0);
    __syncthreads();

    const int NITER = Dx / BK;
    for (int it = 0; it < NITER; ++it) {
        const int buf = it & 1;
        if (it + 1 < NITER) gload((it + 1) * BK);

        const uint32_t* As = sm4 + buf * STG_U32;
        const uint32_t* Bs = As + BM * LDA;
        const int mbase = wm * 64;
        const int nbase = wn * 64;
#pragma unroll
        for (int ks = 0; ks < 2; ks++) {
            const int k = ks * 8;
            uint32_t af[4][4], bf[8][2];
#pragma unroll
            for (int mt = 0; mt < 4; mt++) {
                const uint32_t* p = As + (mbase + mt * 16 + lr) * LDA + k + lc;
                af[mt][0] = p[0];
                af[mt][2] = p[4];
                af[mt][1] = p[8 * LDA];
                af[mt][3] = p[8 * LDA + 4];
            }
#pragma unroll
            for (int nt = 0; nt < 8; nt++) {
                const uint32_t* p = Bs + (nbase + nt * 8 + lr) * LDA + k + lc;
                bf[nt][0] = p[0];
                bf[nt][1] = p[4];
            }
#pragma unroll
            for (int mt = 0; mt < 4; mt++)
#pragma unroll
                for (int nt = 0; nt < 8; nt++)
                    mma16n8k8(c[mt][nt], af[mt], bf[nt]);
        }
        __syncthreads();
        if (it + 1 < NITER) {
            sstore((it + 1) & 1);
            __syncthreads();
        }
    }

#pragma unroll
    for (int mt = 0; mt < 4; mt++) {
        const int mA = m0 + wm * 64 + mt * 16 + lr;
        const int mB = mA + 8;
#pragma unroll
        for (int nt = 0; nt < 8; nt++) {
            const int n = n0 + wn * 64 + nt * 8 + 2 * lc;
            const float bn0 = bias[n], bn1 = bias[n + 1];
            float2 v0 = make_float2(c[mt][nt][0] + bn0, c[mt][nt][1] + bn1);
            float2 v1 = make_float2(c[mt][nt][2] + bn0, c[mt][nt][3] + bn1);
            if (SCATTER) {
                const int h = n >> 6, dk = n & 63;
                const int bA = mA >> 11, lA = mA & (Lx - 1);
                const int bB = mB >> 11, lB = mB & (Lx - 1);
                *(float2*)(out + (((size_t)bA*Hx + h)*Lx + lA)*DKx + dk) = v0;
                *(float2*)(out + (((size_t)bB*Hx + h)*Lx + lB)*DKx + dk) = v1;
            } else {
                *(float2*)(out + (size_t)mA * Dx + n) = v0;
                *(float2*)(out + (size_t)mB * Dx + n) = v1;
            }
        }
    }
}

// ---------------- mma.sync flash attention with temporal bias ----------------
// BM=128 queries per CTA, key tiles of 64. 8 warps, each owns 16 query rows.
// S = QK^T via 3xTF32 (hi/lo compensated, ~fp32 accurate); P@V in plain tf32.
// smem float offsets:
#define O_QH 0
#define O_QL 8704
#define O_KH 17408
#define O_KL 21760
#define O_VS 26112
#define O_PS 30720
#define ATTN_SMEM ((30720 + 8704) * 4)      // 157696 bytes

__global__ __launch_bounds__(256, 1) void k_attn_mma()
{
    extern __shared__ float sm[];
    float* Qh = sm + O_QH;     // [128][68] tf32-hi
    float* Ql = sm + O_QL;     // [128][68] tf32-lo
    float* Kh = sm + O_KH;     // [64][68]
    float* Kl = sm + O_KL;     // [64][68]
    float* Vs = sm + O_VS;     // [64][72]
    float* Ps = sm + O_PS;     // [128][68]
    const uint32_t* Qhu = (const uint32_t*)Qh;
    const uint32_t* Qlu = (const uint32_t*)Ql;
    const uint32_t* Khu = (const uint32_t*)Kh;
    const uint32_t* Klu = (const uint32_t*)Kl;
    const uint32_t* Vsu = (const uint32_t*)Vs;
    const uint32_t* Psu = (const uint32_t*)Ps;

    const int tid = threadIdx.x;
    const int wid = tid >> 5, lane = tid & 31;
    const int lr = lane >> 2, lc = lane & 3;
    const int qt = gridDim.x - 1 - blockIdx.x;      // largest tiles first
    const int bh = blockIdx.y;
    const int b = bh >> 4, h = bh & 15;
    const int qi0 = qt * 128;
    const int r0 = wid * 16;

    const float* Qg = g_Q + (size_t)bh*Lx*DKx + (size_t)qi0*DKx;
    const float* Kg = g_K + (size_t)bh*Lx*DKx;
    const float* Vg = g_V + (size_t)bh*Lx*DKx;
    const float* biasB = g_bias + (size_t)b*Lx*Lx;

    // load Q tile (128x64) -> hi/lo tf32 smem
#pragma unroll
    for (int t = 0; t < 8; t++) {
        int i = tid + t * 256;          // 0..2047 float4s
        int row = i >> 4, q4 = i & 15;
        float4 v = *(const float4*)(Qg + (size_t)row * DKx + q4 * 4);
        float* ph = Qh + row * 68 + q4 * 4;
        float* pl = Ql + row * 68 + q4 * 4;
        split_tf32(v.x, ph[0], pl[0]);
        split_tf32(v.y, ph[1], pl[1]);
        split_tf32(v.z, ph[2], pl[2]);
        split_tf32(v.w, ph[3], pl[3]);
    }

    float cO[8][4];
#pragma unroll
    for (int nt = 0; nt < 8; nt++)
#pragma unroll
        for (int q = 0; q < 4; q++) cO[nt][q] = 0.f;
    float mA = -1e30f, mB = -1e30f, lA = 0.f, lB = 0.f;

    const int qrA = qi0 + r0 + lr;
    const int qrB = qrA + 8;
    const int nkt = 2 * qt + 2;

    for (int kt = 0; kt < nkt; kt++) {
        const int kj0 = kt * 64;
        __syncthreads();
        // load K (hi/lo) and V tiles
#pragma unroll
        for (int t = 0; t < 4; t++) {
            int i = tid + t * 256;       // 0..1023 float4s
            int row = i >> 4, q4 = i & 15;
            float4 kv = *(const float4*)(Kg + (size_t)(kj0 + row) * DKx + q4 * 4);
            float* ph = Kh + row * 68 + q4 * 4;
            float* pl = Kl + row * 68 + q4 * 4;
            split_tf32(kv.x, ph[0], pl[0]);
            split_tf32(kv.y, ph[1], pl[1]);
            split_tf32(kv.z, ph[2], pl[2]);
            split_tf32(kv.w, ph[3], pl[3]);
            float4 vv = *(const float4*)(Vg + (size_t)(kj0 + row) * DKx + q4 * 4);
            float* pv = Vs + row * 72 + q4 * 4;
            pv[0] = __uint_as_float(to_tf32(vv.x));
            pv[1] = __uint_as_float(to_tf32(vv.y));
            pv[2] = __uint_as_float(to_tf32(vv.z));
            pv[3] = __uint_as_float(to_tf32(vv.w));
        }
        __syncthreads();

        // ---- S = Q K^T : 3xTF32 ----
        float cS[8][4];
#pragma unroll
        for (int nt = 0; nt < 8; nt++)
#pragma unroll
            for (int q = 0; q < 4; q++) cS[nt][q] = 0.f;

#pragma unroll
        for (int ks = 0; ks < 8; ks++) {
            const int k = ks * 8;
            uint32_t aH[4], aL[4];
            {
                const uint32_t* p = Qhu + (r0 + lr) * 68 + k + lc;
                aH[0] = p[0]; aH[2] = p[4]; aH[1] = p[8*68]; aH[3] = p[8*68 + 4];
                const uint32_t* q2 = Qlu + (r0 + lr) * 68 + k + lc;
                aL[0] = q2[0]; aL[2] = q2[4]; aL[1] = q2[8*68]; aL[3] = q2[8*68 + 4];
            }
#pragma unroll
            for (int nt = 0; nt < 8; nt++) {
                uint32_t bH[2], bL[2];
                const uint32_t* p = Khu + (nt * 8 + lr) * 68 + k + lc;
                bH[0] = p[0]; bH[1] = p[4];
                const uint32_t* q2 = Klu + (nt * 8 + lr) * 68 + k + lc;
                bL[0] = q2[0]; bL[1] = q2[4];
                mma16n8k8(cS[nt], aH, bH);
                mma16n8k8(cS[nt], aH, bL);
                mma16n8k8(cS[nt], aL, bH);
            }
        }

        // ---- bias + causal mask + online softmax ----
        const bool domask = (kt >= 2 * qt);
        float rmA = -1e30f, rmB = -1e30f;
#pragma unroll
        for (int nt = 0; nt < 8; nt++) {
            const int kc = kj0 + nt * 8 + 2 * lc;
            float2 biA = *(const float2*)(biasB + (size_t)qrA * Lx + kc);
            float2 biB = *(const float2*)(biasB + (size_t)qrB * Lx + kc);
            float v0 = fmaf(cS[nt][0], 0.125f, biA.x);
            float v1 = fmaf(cS[nt][1], 0.125f, biA.y);
            float v2 = fmaf(cS[nt][2], 0.125f, biB.x);
            float v3 = fmaf(cS[nt][3], 0.125f, biB.y);
            if (domask) {
                if (kc     > qrA) v0 = -1e30f;
                if (kc + 1 > qrA) v1 = -1e30f;
                if (kc     > qrB) v2 = -1e30f;
                if (kc + 1 > qrB) v3 = -1e30f;
            }
            cS[nt][0] = v0; cS[nt][1] = v1; cS[nt][2] = v2; cS[nt][3] = v3;
            rmA = fmaxf(rmA, fmaxf(v0, v1));
            rmB = fmaxf(rmB, fmaxf(v2, v3));
        }
        rmA = fmaxf(rmA, __shfl_xor_sync(0xffffffffu, rmA, 1));
        rmA = fmaxf(rmA, __shfl_xor_sync(0xffffffffu, rmA, 2));
        rmB = fmaxf(rmB, __shfl_xor_sync(0xffffffffu, rmB, 1));
        rmB = fmaxf(rmB, __shfl_xor_sync(0xffffffffu, rmB, 2));

        const float mnA = fmaxf(mA, rmA);
        const float mnB = fmaxf(mB, rmB);
        const float scA = fexp(mA - mnA);
        const float scB = fexp(mB - mnB);
        mA = mnA; mB = mnB;

        float rsA = 0.f, rsB = 0.f;
#pragma unroll
        for (int nt = 0; nt < 8; nt++) {
            float p0 = fexp(cS[nt][0] - mnA);
            float p1 = fexp(cS[nt][1] - mnA);
            float p2 = fexp(cS[nt][2] - mnB);
            float p3 = fexp(cS[nt][3] - mnB);
            rsA += p0 + p1;
            rsB += p2 + p3;
            cS[nt][0] = p0; cS[nt][1] = p1; cS[nt][2] = p2; cS[nt][3] = p3;
        }
        rsA += __shfl_xor_sync(0xffffffffu, rsA, 1);
        rsA += __shfl_xor_sync(0xffffffffu, rsA, 2);
        rsB += __shfl_xor_sync(0xffffffffu, rsB, 1);
        rsB += __shfl_xor_sync(0xffffffffu, rsB, 2);
        lA = lA * scA + rsA;
        lB = lB * scB + rsB;
#pragma unroll
        for (int nt = 0; nt < 8; nt++) {
            cO[nt][0] *= scA; cO[nt][1] *= scA;
            cO[nt][2] *= scB; cO[nt][3] *= scB;
        }

        // ---- store P (tf32) ----
#pragma unroll
        for (int nt = 0; nt < 8; nt++) {
            float* pA = Ps + (r0 + lr) * 68 + nt * 8 + 2 * lc;
            float* pB = Ps + (r0 + lr + 8) * 68 + nt * 8 + 2 * lc;
            pA[0] = __uint_as_float(to_tf32(cS[nt][0]));
            pA[1] = __uint_as_float(to_tf32(cS[nt][1]));
            pB[0] = __uint_as_float(to_tf32(cS[nt][2]));
            pB[1] = __uint_as_float(to_tf32(cS[nt][3]));
        }
        __syncthreads();

        // ---- O += P @ V ----
#pragma unroll
        for (int ks = 0; ks < 8; ks++) {
            const int k = ks * 8;
            uint32_t aP[4];
            const uint32_t* p = Psu + (r0 + lr) * 68 + k + lc;
            aP[0] = p[0]; aP[2] = p[4]; aP[1] = p[8*68]; aP[3] = p[8*68 + 4];
#pragma unroll
            for (int nt = 0; nt < 8; nt++) {
                uint32_t bV[2];
                bV[0] = Vsu[(k + lc) * 72 + nt * 8 + lr];
                bV[1] = Vsu[(k + lc + 4) * 72 + nt * 8 + lr];
                mma16n8k8(cO[nt], aP, bV);
            }
        }
    }

    // ---- normalize + write to g_attn [B,L,H*DK] ----
    const float invA = 1.0f / lA;
    const float invB = 1.0f / lB;
    float* oA = g_attn + ((size_t)b * Lx + qrA) * Dx + h * DKx;
    float* oB = g_attn + ((size_t)b * Lx + qrB) * Dx + h * DKx;
#pragma unroll
    for (int nt = 0; nt < 8; nt++) {
        const int n = nt * 8 + 2 * lc;
        *(float2*)(oA + n) = make_float2(cO[nt][0] * invA, cO[nt][1] * invA);
        *(float2*)(oB + n) = make_float2(cO[nt][2] * invB, cO[nt][3] * invB);
    }
}

// ---------------- launch ----------------
extern "C" void kernel_launch(void* const* d_in, const int* in_sizes, int n_in,
                              void* d_out, int out_size)
{
    const float* x   = (const float*)d_in[0];
    const float* ts  = (const float*)d_in[1];
    const float* Wq  = (const float*)d_in[4];
    const float* bq  = (const float*)d_in[5];
    const float* Wk  = (const float*)d_in[6];
    const float* bk  = (const float*)d_in[7];
    const float* Wv  = (const float*)d_in[8];
    const float* bv  = (const float*)d_in[9];
    const float* Wo  = (const float*)d_in[10];
    const float* bo  = (const float*)d_in[11];
    const float* lam = (const float*)d_in[12];
    float* out = (float*)d_out;

    k_denom<<<1, 1>>>(ts, lam);
    k_bias<<<(Bx*Lx*Lx)/256, 256>>>(ts);

    cudaFuncSetAttribute(k_gemm_mma<true>,  cudaFuncAttributeMaxDynamicSharedMemorySize, GEMM_SMEM);
    cudaFuncSetAttribute(k_gemm_mma<false>, cudaFuncAttributeMaxDynamicSharedMemorySize, GEMM_SMEM);
    cudaFuncSetAttribute(k_attn_mma, cudaFuncAttributeMaxDynamicSharedMemorySize, ATTN_SMEM);

    // Q/K/V projections
    k_gemm_mma<true><<<dim3(Dx/BN, (Bx*Lx)/BM, 3), 256, GEMM_SMEM>>>(
        x, Wq, bq, Wk, bk, Wv, bv, nullptr);

    // flash attention (tensor path)
    k_attn_mma<<<dim3(Lx/128, BHx), 256, ATTN_SMEM>>>();

    // output projection
    k_gemm_mma<false><<<dim3(Dx/BN, (Bx*Lx)/BM, 1), 256, GEMM_SMEM>>>(
        nullptr, Wo, bo, nullptr, nullptr, nullptr, nullptr, out);
}

// round 6
// speedup vs baseline: 2.6017x; 1.1774x over previous
#include <cuda_runtime.h>
#include <cuda_bf16.h>
#include <math.h>
#include <stdint.h>

// Problem constants
#define Bx  2
#define Lx  2048
#define Dx  1024
#define Hx  16
#define DKx 64
#define BHx (Bx*Hx)

// ---------------- device scratch (no allocations allowed) ----------------
__device__ float g_Q[(size_t)BHx*Lx*DKx];      // [B,H,L,DK]
__device__ float g_K[(size_t)BHx*Lx*DKx];
__device__ float g_V[(size_t)BHx*Lx*DKx];
__device__ float g_attn[(size_t)Bx*Lx*Dx];     // [B,L,H*DK]
__device__ float g_bias[(size_t)Bx*Lx*Lx];     // -|lam|*log1p(|ti-tj|/denom)
__device__ float g_scal[2];                    // [0]=1/denom, [1]=-|lam|

// ---------------- helpers ----------------
__device__ __forceinline__ uint32_t to_tf32(float x) {
    uint32_t r;
    asm("cvt.rna.tf32.f32 %0, %1;" : "=r"(r) : "f"(x));
    return r;
}
__device__ __forceinline__ float tf32f(float x) { return __uint_as_float(to_tf32(x)); }

// split two floats into packed bf16x2 hi and lo (hi+lo ~ 16-bit mantissa accuracy)
__device__ __forceinline__ void split2(float2 v, uint32_t& hi, uint32_t& lo) {
    __nv_bfloat162 h = __floats2bfloat162_rn(v.x, v.y);
    float hx = __bfloat162float(h.x);
    float hy = __bfloat162float(h.y);
    __nv_bfloat162 l = __floats2bfloat162_rn(v.x - hx, v.y - hy);
    hi = *(uint32_t*)&h;
    lo = *(uint32_t*)&l;
}

__device__ __forceinline__ void mma16n8k8(float* c, const uint32_t* a, const uint32_t* b) {
    asm volatile(
        "mma.sync.aligned.m16n8k8.row.col.f32.tf32.tf32.f32 "
        "{%0,%1,%2,%3}, {%4,%5,%6,%7}, {%8,%9}, {%0,%1,%2,%3};"
        : "+f"(c[0]), "+f"(c[1]), "+f"(c[2]), "+f"(c[3])
        : "r"(a[0]), "r"(a[1]), "r"(a[2]), "r"(a[3]), "r"(b[0]), "r"(b[1]));
}
__device__ __forceinline__ void mma_bf16(float* c, const uint32_t* a, uint32_t b0, uint32_t b1) {
    asm volatile(
        "mma.sync.aligned.m16n8k16.row.col.f32.bf16.bf16.f32 "
        "{%0,%1,%2,%3}, {%4,%5,%6,%7}, {%8,%9}, {%0,%1,%2,%3};"
        : "+f"(c[0]), "+f"(c[1]), "+f"(c[2]), "+f"(c[3])
        : "r"(a[0]), "r"(a[1]), "r"(a[2]), "r"(a[3]), "r"(b0), "r"(b1));
}

// Fast exp on the FMA pipe (clamps below -80 -> ~0).
__device__ __forceinline__ float fexp(float x) {
    x = fmaxf(x, -80.0f);
    float z = fmaf(x, 1.4426950408889634f, 12582912.0f);
    int   ni = __float_as_int(z) - 0x4B400000;
    float fn = z - 12582912.0f;
    float f  = fmaf(x, 1.4426950408889634f, -fn);
    float p = 0.0013333558f;
    p = fmaf(p, f, 0.0096181291f);
    p = fmaf(p, f, 0.0555041087f);
    p = fmaf(p, f, 0.2402265069f);
    p = fmaf(p, f, 0.6931471806f);
    p = fmaf(p, f, 1.0f);
    return __int_as_float(__float_as_int(p) + (ni << 23));
}

// ---------------- denom + lam scalars ----------------
__global__ void k_denom(const float* __restrict__ ts, const float* __restrict__ lam)
{
    float m = 1.0f;
    for (int b = 0; b < Bx; b++) {
        float d = ts[b*Lx + (Lx-1)] - ts[b*Lx + 0];
        m = fmaxf(m, d);
    }
    g_scal[0] = 1.0f / m;
    g_scal[1] = -fabsf(lam[0]);
}

// ---------------- temporal bias precompute ----------------
__global__ __launch_bounds__(256) void k_bias(const float* __restrict__ ts)
{
    long idx = (long)blockIdx.x * 256 + threadIdx.x;
    int  j = (int)(idx & (Lx-1));
    long t = idx >> 11;
    int  i = (int)(t & (Lx-1));
    int  b = (int)(t >> 11);
    float d = fabsf(ts[b*Lx + i] - ts[b*Lx + j]);
    g_bias[idx] = g_scal[1] * log1pf(d * g_scal[0]);
}

// ---------------- tf32 mma.sync GEMM (unchanged) ----------------
#define BM 128
#define BN 256
#define BK 16
#define LDA 20
#define STG_U32 ((BM + BN) * LDA)
#define GEMM_SMEM (2 * STG_U32 * 4)

template<bool SCATTER>
__global__ __launch_bounds__(256, 1) void k_gemm_mma(
    const float* __restrict__ Ain,
    const float* __restrict__ W0, const float* __restrict__ b0,
    const float* __restrict__ W1, const float* __restrict__ b1,
    const float* __restrict__ W2, const float* __restrict__ b2,
    float* __restrict__ outp)
{
    extern __shared__ uint32_t sm4[];

    const float* A;
    const float* W;
    const float* bias;
    float* out;
    if (SCATTER) {
        A = Ain;
        if (blockIdx.z == 0)      { W = W0; bias = b0; out = g_Q; }
        else if (blockIdx.z == 1) { W = W1; bias = b1; out = g_K; }
        else                      { W = W2; bias = b2; out = g_V; }
    } else {
        A = g_attn; W = W0; bias = b0; out = outp;
    }

    const int tid = threadIdx.x;
    const int wid = tid >> 5;
    const int lane = tid & 31;
    const int wm = wid >> 2;
    const int wn = wid & 3;
    const int lr = lane >> 2;
    const int lc = lane & 3;

    const int m0 = blockIdx.y * BM;
    const int n0 = blockIdx.x * BN;

    float c[4][8][4];
#pragma unroll
    for (int i = 0; i < 4; i++)
#pragma unroll
        for (int j = 0; j < 8; j++)
#pragma unroll
            for (int q = 0; q < 4; q++) c[i][j][q] = 0.f;

    float4 pa[2], pb[4];

    auto gload = [&](int k0) {
#pragma unroll
        for (int t = 0; t < 2; t++) {
            int i = tid + t * 256;
            int row = i >> 2, q = i & 3;
            pa[t] = *(const float4*)(A + (size_t)(m0 + row) * Dx + k0 + q * 4);
        }
#pragma unroll
        for (int t = 0; t < 4; t++) {
            int i = tid + t * 256;
            int row = i >> 2, q = i & 3;
            pb[t] = *(const float4*)(W + (size_t)(n0 + row) * Dx + k0 + q * 4);
        }
    };
    auto sstore = [&](int buf) {
        uint32_t* As = sm4 + buf * STG_U32;
        uint32_t* Bs = As + BM * LDA;
#pragma unroll
        for (int t = 0; t < 2; t++) {
            int i = tid + t * 256;
            int row = i >> 2, q = i & 3;
            uint32_t* p = As + row * LDA + q * 4;
            p[0] = to_tf32(pa[t].x); p[1] = to_tf32(pa[t].y);
            p[2] = to_tf32(pa[t].z); p[3] = to_tf32(pa[t].w);
        }
#pragma unroll
        for (int t = 0; t < 4; t++) {
            int i = tid + t * 256;
            int row = i >> 2, q = i & 3;
            uint32_t* p = Bs + row * LDA + q * 4;
            p[0] = to_tf32(pb[t].x); p[1] = to_tf32(pb[t].y);
            p[2] = to_tf32(pb[t].z); p[3] = to_tf32(pb[t].w);
        }
    };

    gload(0);
    sstore(0);
    __syncthreads();

    const int NITER = Dx / BK;
    for (int it = 0; it < NITER; ++it) {
        const int buf = it & 1;
        if (it + 1 < NITER) gload((it + 1) * BK);

        const uint32_t* As = sm4 + buf * STG_U32;
        const uint32_t* Bs = As + BM * LDA;
        const int mbase = wm * 64;
        const int nbase = wn * 64;
#pragma unroll
        for (int ks = 0; ks < 2; ks++) {
            const int k = ks * 8;
            uint32_t af[4][4], bf[8][2];
#pragma unroll
            for (int mt = 0; mt < 4; mt++) {
                const uint32_t* p = As + (mbase + mt * 16 + lr) * LDA + k + lc;
                af[mt][0] = p[0];
                af[mt][2] = p[4];
                af[mt][1] = p[8 * LDA];
                af[mt][3] = p[8 * LDA + 4];
            }
#pragma unroll
            for (int nt = 0; nt < 8; nt++) {
                const uint32_t* p = Bs + (nbase + nt * 8 + lr) * LDA + k + lc;
                bf[nt][0] = p[0];
                bf[nt][1] = p[4];
            }
#pragma unroll
            for (int mt = 0; mt < 4; mt++)
#pragma unroll
                for (int nt = 0; nt < 8; nt++)
                    mma16n8k8(c[mt][nt], af[mt], bf[nt]);
        }
        __syncthreads();
        if (it + 1 < NITER) {
            sstore((it + 1) & 1);
            __syncthreads();
        }
    }

#pragma unroll
    for (int mt = 0; mt < 4; mt++) {
        const int mA = m0 + wm * 64 + mt * 16 + lr;
        const int mB = mA + 8;
#pragma unroll
        for (int nt = 0; nt < 8; nt++) {
            const int n = n0 + wn * 64 + nt * 8 + 2 * lc;
            const float bn0 = bias[n], bn1 = bias[n + 1];
            float2 v0 = make_float2(c[mt][nt][0] + bn0, c[mt][nt][1] + bn1);
            float2 v1 = make_float2(c[mt][nt][2] + bn0, c[mt][nt][3] + bn1);
            if (SCATTER) {
                const int h = n >> 6, dk = n & 63;
                const int bA = mA >> 11, lA = mA & (Lx - 1);
                const int bB = mB >> 11, lB = mB & (Lx - 1);
                *(float2*)(out + (((size_t)bA*Hx + h)*Lx + lA)*DKx + dk) = v0;
                *(float2*)(out + (((size_t)bB*Hx + h)*Lx + lB)*DKx + dk) = v1;
            } else {
                *(float2*)(out + (size_t)mA * Dx + n) = v0;
                *(float2*)(out + (size_t)mB * Dx + n) = v1;
            }
        }
    }
}

// ---------------- mma.sync flash attention, high-occupancy version ----------------
// 128 threads (4 warps), BM=64 queries, key tiles of 64.
// Q frags (bf16 hi/lo) in registers, loaded once. S = 3x bf16 m16n8k16.
// PV in tf32 m16n8k8. smem ~53KB -> 3 CTAs/SM.
// smem u32 offsets:
#define AO_KH 0                    // [64][36] u32 (packed bf16x2 hi)
#define AO_KL 2304                 // [64][36] u32 (packed bf16x2 lo)
#define AO_V  4608                 // [64][72] float (tf32)
#define AO_P  9216                 // [64][68] float (tf32)
#define ATTN_SMEM ((9216 + 4352) * 4)      // 54272 bytes

__global__ __launch_bounds__(128, 3) void k_attn_mma()
{
    extern __shared__ uint32_t smu[];
    uint32_t* KhU = smu + AO_KH;
    uint32_t* KlU = smu + AO_KL;
    float*    Vs  = (float*)(smu + AO_V);
    float*    Ps  = (float*)(smu + AO_P);
    const uint32_t* VsU = (const uint32_t*)Vs;
    const uint32_t* PsU = (const uint32_t*)Ps;

    const int tid = threadIdx.x;
    const int wid = tid >> 5, lane = tid & 31;
    const int lr = lane >> 2, lc = lane & 3;
    const int qt = gridDim.x - 1 - blockIdx.x;      // largest tiles first
    const int bh = blockIdx.y;
    const int b = bh >> 4, h = bh & 15;
    const int qi0 = qt * 64;
    const int r0 = wid * 16;
    const int qrA = qi0 + r0 + lr;
    const int qrB = qrA + 8;

    const float* Qg = g_Q + (size_t)bh*Lx*DKx;
    const float* Kg = g_K + (size_t)bh*Lx*DKx;
    const float* Vg = g_V + (size_t)bh*Lx*DKx;
    const float* biasB = g_bias + (size_t)b*Lx*Lx;

    // ---- Q fragments (bf16 hi/lo) held in registers for the whole kernel ----
    uint32_t qH[4][4], qL[4][4];
#pragma unroll
    for (int ks = 0; ks < 4; ks++) {
        const int kb = 16 * ks + 2 * lc;
        float2 v;
        v = *(const float2*)(Qg + (size_t)qrA * DKx + kb);
        split2(v, qH[ks][0], qL[ks][0]);
        v = *(const float2*)(Qg + (size_t)qrB * DKx + kb);
        split2(v, qH[ks][1], qL[ks][1]);
        v = *(const float2*)(Qg + (size_t)qrA * DKx + kb + 8);
        split2(v, qH[ks][2], qL[ks][2]);
        v = *(const float2*)(Qg + (size_t)qrB * DKx + kb + 8);
        split2(v, qH[ks][3], qL[ks][3]);
    }

    float cO[8][4];
#pragma unroll
    for (int nt = 0; nt < 8; nt++)
#pragma unroll
        for (int q = 0; q < 4; q++) cO[nt][q] = 0.f;
    float mA = -1e30f, mB = -1e30f, lA = 0.f, lB = 0.f;

    const int nkt = qt + 1;

    for (int kt = 0; kt < nkt; kt++) {
        const int kj0 = kt * 64;
        __syncthreads();       // protect K/V/P from previous iteration readers

        // ---- stage K (bf16 hi/lo) and V (tf32) ----
#pragma unroll
        for (int t = 0; t < 8; t++) {
            int i = tid + t * 128;            // 0..1023 float4 units
            int row = i >> 4, c4 = i & 15;
            float4 kv = *(const float4*)(Kg + (size_t)(kj0 + row) * DKx + c4 * 4);
            uint32_t h0, l0, h1, l1;
            split2(make_float2(kv.x, kv.y), h0, l0);
            split2(make_float2(kv.z, kv.w), h1, l1);
            KhU[row * 36 + c4 * 2]     = h0;
            KhU[row * 36 + c4 * 2 + 1] = h1;
            KlU[row * 36 + c4 * 2]     = l0;
            KlU[row * 36 + c4 * 2 + 1] = l1;
            float4 vv = *(const float4*)(Vg + (size_t)(kj0 + row) * DKx + c4 * 4);
            float* pv = Vs + row * 72 + c4 * 4;
            pv[0] = tf32f(vv.x); pv[1] = tf32f(vv.y);
            pv[2] = tf32f(vv.z); pv[3] = tf32f(vv.w);
        }
        __syncthreads();

        // ---- S = Q K^T : 3x bf16 ----
        float cS[8][4];
#pragma unroll
        for (int nt = 0; nt < 8; nt++)
#pragma unroll
            for (int q = 0; q < 4; q++) cS[nt][q] = 0.f;

#pragma unroll
        for (int ks = 0; ks < 4; ks++) {
#pragma unroll
            for (int nt = 0; nt < 8; nt++) {
                const uint32_t* ph = KhU + (nt * 8 + lr) * 36 + ks * 8 + lc;
                const uint32_t* pl = KlU + (nt * 8 + lr) * 36 + ks * 8 + lc;
                uint32_t bH0 = ph[0], bH1 = ph[4];
                uint32_t bL0 = pl[0], bL1 = pl[4];
                mma_bf16(cS[nt], qH[ks], bH0, bH1);
                mma_bf16(cS[nt], qH[ks], bL0, bL1);
                mma_bf16(cS[nt], qL[ks], bH0, bH1);
            }
        }

        // ---- bias + causal mask + online softmax ----
        const bool domask = (kt == qt);
        float rmA = -1e30f, rmB = -1e30f;
#pragma unroll
        for (int nt = 0; nt < 8; nt++) {
            const int kc = kj0 + nt * 8 + 2 * lc;
            float2 biA = *(const float2*)(biasB + (size_t)qrA * Lx + kc);
            float2 biB = *(const float2*)(biasB + (size_t)qrB * Lx + kc);
            float v0 = fmaf(cS[nt][0], 0.125f, biA.x);
            float v1 = fmaf(cS[nt][1], 0.125f, biA.y);
            float v2 = fmaf(cS[nt][2], 0.125f, biB.x);
            float v3 = fmaf(cS[nt][3], 0.125f, biB.y);
            if (domask) {
                if (kc     > qrA) v0 = -1e30f;
                if (kc + 1 > qrA) v1 = -1e30f;
                if (kc     > qrB) v2 = -1e30f;
                if (kc + 1 > qrB) v3 = -1e30f;
            }
            cS[nt][0] = v0; cS[nt][1] = v1; cS[nt][2] = v2; cS[nt][3] = v3;
            rmA = fmaxf(rmA, fmaxf(v0, v1));
            rmB = fmaxf(rmB, fmaxf(v2, v3));
        }
        rmA = fmaxf(rmA, __shfl_xor_sync(0xffffffffu, rmA, 1));
        rmA = fmaxf(rmA, __shfl_xor_sync(0xffffffffu, rmA, 2));
        rmB = fmaxf(rmB, __shfl_xor_sync(0xffffffffu, rmB, 1));
        rmB = fmaxf(rmB, __shfl_xor_sync(0xffffffffu, rmB, 2));

        const float mnA = fmaxf(mA, rmA);
        const float mnB = fmaxf(mB, rmB);
        const float scA = fexp(mA - mnA);
        const float scB = fexp(mB - mnB);
        mA = mnA; mB = mnB;

        float rsA = 0.f, rsB = 0.f;
#pragma unroll
        for (int nt = 0; nt < 8; nt++) {
            float p0 = fexp(cS[nt][0] - mnA);
            float p1 = fexp(cS[nt][1] - mnA);
            float p2 = fexp(cS[nt][2] - mnB);
            float p3 = fexp(cS[nt][3] - mnB);
            rsA += p0 + p1;
            rsB += p2 + p3;
            cS[nt][0] = p0; cS[nt][1] = p1; cS[nt][2] = p2; cS[nt][3] = p3;
        }
        rsA += __shfl_xor_sync(0xffffffffu, rsA, 1);
        rsA += __shfl_xor_sync(0xffffffffu, rsA, 2);
        rsB += __shfl_xor_sync(0xffffffffu, rsB, 1);
        rsB += __shfl_xor_sync(0xffffffffu, rsB, 2);
        lA = lA * scA + rsA;
        lB = lB * scB + rsB;
#pragma unroll
        for (int nt = 0; nt < 8; nt++) {
            cO[nt][0] *= scA; cO[nt][1] *= scA;
            cO[nt][2] *= scB; cO[nt][3] *= scB;
        }

        // ---- store P (tf32) ----
#pragma unroll
        for (int nt = 0; nt < 8; nt++) {
            float* pA = Ps + (r0 + lr) * 68 + nt * 8 + 2 * lc;
            float* pB = Ps + (r0 + lr + 8) * 68 + nt * 8 + 2 * lc;
            pA[0] = tf32f(cS[nt][0]);
            pA[1] = tf32f(cS[nt][1]);
            pB[0] = tf32f(cS[nt][2]);
            pB[1] = tf32f(cS[nt][3]);
        }
        __syncthreads();

        // ---- O += P @ V (tf32) ----
#pragma unroll
        for (int ks = 0; ks < 8; ks++) {
            const int k = ks * 8;
            uint32_t aP[4];
            const uint32_t* p = PsU + (r0 + lr) * 68 + k + lc;
            aP[0] = p[0]; aP[2] = p[4]; aP[1] = p[8 * 68]; aP[3] = p[8 * 68 + 4];
#pragma unroll
            for (int nt = 0; nt < 8; nt++) {
                uint32_t bV[2];
                bV[0] = VsU[(k + lc) * 72 + nt * 8 + lr];
                bV[1] = VsU[(k + lc + 4) * 72 + nt * 8 + lr];
                mma16n8k8(cO[nt], aP, bV);
            }
        }
    }

    // ---- normalize + write to g_attn [B,L,H*DK] ----
    const float invA = 1.0f / lA;
    const float invB = 1.0f / lB;
    float* oA = g_attn + ((size_t)b * Lx + qrA) * Dx + h * DKx;
    float* oB = g_attn + ((size_t)b * Lx + qrB) * Dx + h * DKx;
#pragma unroll
    for (int nt = 0; nt < 8; nt++) {
        const int n = nt * 8 + 2 * lc;
        *(float2*)(oA + n) = make_float2(cO[nt][0] * invA, cO[nt][1] * invA);
        *(float2*)(oB + n) = make_float2(cO[nt][2] * invB, cO[nt][3] * invB);
    }
}

// ---------------- launch ----------------
extern "C" void kernel_launch(void* const* d_in, const int* in_sizes, int n_in,
                              void* d_out, int out_size)
{
    const float* x   = (const float*)d_in[0];
    const float* ts  = (const float*)d_in[1];
    const float* Wq  = (const float*)d_in[4];
    const float* bq  = (const float*)d_in[5];
    const float* Wk  = (const float*)d_in[6];
    const float* bk  = (const float*)d_in[7];
    const float* Wv  = (const float*)d_in[8];
    const float* bv  = (const float*)d_in[9];
    const float* Wo  = (const float*)d_in[10];
    const float* bo  = (const float*)d_in[11];
    const float* lam = (const float*)d_in[12];
    float* out = (float*)d_out;

    k_denom<<<1, 1>>>(ts, lam);
    k_bias<<<(Bx*Lx*Lx)/256, 256>>>(ts);

    cudaFuncSetAttribute(k_gemm_mma<true>,  cudaFuncAttributeMaxDynamicSharedMemorySize, GEMM_SMEM);
    cudaFuncSetAttribute(k_gemm_mma<false>, cudaFuncAttributeMaxDynamicSharedMemorySize, GEMM_SMEM);
    cudaFuncSetAttribute(k_attn_mma, cudaFuncAttributeMaxDynamicSharedMemorySize, ATTN_SMEM);

    // Q/K/V projections
    k_gemm_mma<true><<<dim3(Dx/BN, (Bx*Lx)/BM, 3), 256, GEMM_SMEM>>>(
        x, Wq, bq, Wk, bk, Wv, bv, nullptr);

    // flash attention (tensor path, 64-row query tiles)
    k_attn_mma<<<dim3(Lx/64, BHx), 128, ATTN_SMEM>>>();

    // output projection
    k_gemm_mma<false><<<dim3(Dx/BN, (Bx*Lx)/BM, 1), 256, GEMM_SMEM>>>(
        nullptr, Wo, bo, nullptr, nullptr, nullptr, nullptr, out);
}